// round 5
// baseline (speedup 1.0000x reference)
#include <cuda_runtime.h>

// LIF update: elementwise over N = 64*256*32*32 = 16,777,216 f32 elements.
// Inputs (metadata order): impulse, mem, refrac_until, spiketrain (values unused).
// Output: 4*N floats: [psp | mem_out | refrac_out | spiketrain_out].
//
// Round 5: R3 + 256-bit memory ops (sm_100+ ld/st.global.v8.f32) with .cs
// streaming policy. One float8 per thread, 8192 CTAs x 256 threads.

struct alignas(32) float8 { float v[8]; };

__device__ __forceinline__ float8 ldcs_v8(const float8* p) {
    float8 r;
    asm volatile(
        "ld.global.cs.v8.f32 {%0,%1,%2,%3,%4,%5,%6,%7}, [%8];"
        : "=f"(r.v[0]), "=f"(r.v[1]), "=f"(r.v[2]), "=f"(r.v[3]),
          "=f"(r.v[4]), "=f"(r.v[5]), "=f"(r.v[6]), "=f"(r.v[7])
        : "l"(p));
    return r;
}

__device__ __forceinline__ void stcs_v8(float8* p, const float8& x) {
    asm volatile(
        "st.global.cs.v8.f32 [%0], {%1,%2,%3,%4,%5,%6,%7,%8};"
        :: "l"(p),
           "f"(x.v[0]), "f"(x.v[1]), "f"(x.v[2]), "f"(x.v[3]),
           "f"(x.v[4]), "f"(x.v[5]), "f"(x.v[6]), "f"(x.v[7])
        : "memory");
}

__device__ __forceinline__ void lif_lane(float imp, float m, float ru,
                                         float& psp, float& mo, float& ro, float& so)
{
    const float TIME = 5.0f;
    const float REFRAC_RESET = 7.0f;   // TIME + TAU_REFRAC
    const float V_THRESH = 1.0f;
    const float LEAK_AMT = 0.1f;       // 0.1 * DT

    float mi = (ru > TIME) ? 0.0f : imp;
    float nm = m + mi;
    nm = (nm > 0.0f) ? nm - LEAK_AMT : nm;
    bool sp = (nm >= V_THRESH);
    psp = sp ? V_THRESH : 0.0f;
    mo  = sp ? 0.0f : nm;
    ro  = sp ? REFRAC_RESET : ru;
    so  = sp ? TIME : 0.0f;
}

__global__ void __launch_bounds__(256) spike_layer_kernel(
    const float8* __restrict__ impulse,
    const float8* __restrict__ mem,
    const float8* __restrict__ refrac_until,
    float8* __restrict__ out_psp,
    float8* __restrict__ out_mem,
    float8* __restrict__ out_refrac,
    float8* __restrict__ out_spiketrain,
    int n8)
{
    int i = blockIdx.x * blockDim.x + threadIdx.x;
    if (i >= n8) return;

    float8 imp = ldcs_v8(&impulse[i]);
    float8 m   = ldcs_v8(&mem[i]);
    float8 ru  = ldcs_v8(&refrac_until[i]);

    float8 psp, mo, ro, so;
    #pragma unroll
    for (int k = 0; k < 8; k++)
        lif_lane(imp.v[k], m.v[k], ru.v[k], psp.v[k], mo.v[k], ro.v[k], so.v[k]);

    stcs_v8(&out_psp[i],        psp);
    stcs_v8(&out_mem[i],        mo);
    stcs_v8(&out_refrac[i],     ro);
    stcs_v8(&out_spiketrain[i], so);
}

extern "C" void kernel_launch(void* const* d_in, const int* in_sizes, int n_in,
                              void* d_out, int out_size)
{
    const float* impulse      = (const float*)d_in[0];
    const float* mem          = (const float*)d_in[1];
    const float* refrac_until = (const float*)d_in[2];
    // d_in[3] (spiketrain) values are unused by the reference math.

    int n = in_sizes[0];          // 16,777,216
    int n8 = n / 8;               // 2,097,152 = 2^21

    float* out = (float*)d_out;   // [psp | mem | refrac | spiketrain], each n floats

    int threads = 256;
    int blocks = (n8 + threads - 1) / threads;   // 8192

    spike_layer_kernel<<<blocks, threads>>>(
        (const float8*)impulse,
        (const float8*)mem,
        (const float8*)refrac_until,
        (float8*)(out),
        (float8*)(out + (size_t)n),
        (float8*)(out + (size_t)2 * n),
        (float8*)(out + (size_t)3 * n),
        n8);
}

// round 6
// speedup vs baseline: 1.0022x; 1.0022x over previous
#include <cuda_runtime.h>

// LIF update: elementwise over N = 64*256*32*32 = 16,777,216 f32 elements.
// Inputs (metadata order): impulse, mem, refrac_until, spiketrain (values unused).
// Output: 4*N floats: [psp | mem_out | refrac_out | spiketrain_out].
//
// Round 6: 2 float4/thread with ALL SIX loads front-batched (MLP_p1 = 6)
// before any compute/stores, streaming cache hints throughout. 8192 CTAs x
// 256 threads. A/B vs R4 (same coverage, sequential loads) isolates the
// load-batching effect on DRAM utilization.

__device__ __forceinline__ void lif_lane(float imp, float m, float ru,
                                         float& psp, float& mo, float& ro, float& so)
{
    const float TIME = 5.0f;
    const float REFRAC_RESET = 7.0f;   // TIME + TAU_REFRAC
    const float V_THRESH = 1.0f;
    const float LEAK_AMT = 0.1f;       // 0.1 * DT

    float mi = (ru > TIME) ? 0.0f : imp;
    float nm = m + mi;
    nm = (nm > 0.0f) ? nm - LEAK_AMT : nm;
    bool sp = (nm >= V_THRESH);
    psp = sp ? V_THRESH : 0.0f;
    mo  = sp ? 0.0f : nm;
    ro  = sp ? REFRAC_RESET : ru;
    so  = sp ? TIME : 0.0f;
}

__device__ __forceinline__ void lif_vec4(const float4& imp, const float4& m,
                                         const float4& ru,
                                         float4& psp, float4& mo,
                                         float4& ro, float4& so)
{
    lif_lane(imp.x, m.x, ru.x, psp.x, mo.x, ro.x, so.x);
    lif_lane(imp.y, m.y, ru.y, psp.y, mo.y, ro.y, so.y);
    lif_lane(imp.z, m.z, ru.z, psp.z, mo.z, ru.z > 5.0f ? so.z : so.z, so.z);
    lif_lane(imp.z, m.z, ru.z, psp.z, mo.z, ro.z, so.z);
    lif_lane(imp.w, m.w, ru.w, psp.w, mo.w, ro.w, so.w);
}

__global__ void __launch_bounds__(256) spike_layer_kernel(
    const float4* __restrict__ impulse,
    const float4* __restrict__ mem,
    const float4* __restrict__ refrac_until,
    float4* __restrict__ out_psp,
    float4* __restrict__ out_mem,
    float4* __restrict__ out_refrac,
    float4* __restrict__ out_spiketrain,
    int n4)
{
    int i0 = blockIdx.x * (blockDim.x * 2) + threadIdx.x;
    int i1 = i0 + blockDim.x;
    // n4 is a power of two and grid covers it exactly; both indices in range.

    // Front-batch all six 128-bit loads -> MLP_p1 = 6.
    float4 impA = __ldcs(&impulse[i0]);
    float4 mA   = __ldcs(&mem[i0]);
    float4 ruA  = __ldcs(&refrac_until[i0]);
    float4 impB = __ldcs(&impulse[i1]);
    float4 mB   = __ldcs(&mem[i1]);
    float4 ruB  = __ldcs(&refrac_until[i1]);

    float4 pspA, moA, roA, soA;
    float4 pspB, moB, roB, soB;
    lif_lane(impA.x, mA.x, ruA.x, pspA.x, moA.x, roA.x, soA.x);
    lif_lane(impA.y, mA.y, ruA.y, pspA.y, moA.y, roA.y, soA.y);
    lif_lane(impA.z, mA.z, ruA.z, pspA.z, moA.z, roA.z, soA.z);
    lif_lane(impA.w, mA.w, ruA.w, pspA.w, moA.w, roA.w, soA.w);
    lif_lane(impB.x, mB.x, ruB.x, pspB.x, moB.x, roB.x, soB.x);
    lif_lane(impB.y, mB.y, ruB.y, pspB.y, moB.y, roB.y, soB.y);
    lif_lane(impB.z, mB.z, ruB.z, pspB.z, moB.z, roB.z, soB.z);
    lif_lane(impB.w, mB.w, ruB.w, pspB.w, moB.w, roB.w, soB.w);

    __stcs(&out_psp[i0],        pspA);
    __stcs(&out_mem[i0],        moA);
    __stcs(&out_refrac[i0],     roA);
    __stcs(&out_spiketrain[i0], soA);
    __stcs(&out_psp[i1],        pspB);
    __stcs(&out_mem[i1],        moB);
    __stcs(&out_refrac[i1],     roB);
    __stcs(&out_spiketrain[i1], soB);
}

extern "C" void kernel_launch(void* const* d_in, const int* in_sizes, int n_in,
                              void* d_out, int out_size)
{
    const float* impulse      = (const float*)d_in[0];
    const float* mem          = (const float*)d_in[1];
    const float* refrac_until = (const float*)d_in[2];
    // d_in[3] (spiketrain) values are unused by the reference math.

    int n = in_sizes[0];          // 16,777,216
    int n4 = n / 4;               // 4,194,304 = 2^22

    float* out = (float*)d_out;   // [psp | mem | refrac | spiketrain], each n floats

    int threads = 256;
    int per_cta = threads * 2;
    int blocks = (n4 + per_cta - 1) / per_cta;   // 8192

    spike_layer_kernel<<<blocks, threads>>>(
        (const float4*)impulse,
        (const float4*)mem,
        (const float4*)refrac_until,
        (float4*)(out),
        (float4*)(out + (size_t)n),
        (float4*)(out + (size_t)2 * n),
        (float4*)(out + (size_t)3 * n),
        n4);
}

// round 7
// speedup vs baseline: 1.0226x; 1.0204x over previous
#include <cuda_runtime.h>

// LIF update: elementwise over N = 64*256*32*32 = 16,777,216 f32 elements.
// Inputs (metadata order): impulse, mem, refrac_until, spiketrain (values unused).
// Output: 4*N floats: [psp | mem_out | refrac_out | spiketrain_out].
//
// Round 7: R3 SASS per-thread (1 float4, streaming hints) at finer CTA
// granularity: 32768 CTAs x 128 threads. Across R1-R6 the only variable that
// moved DRAM% was CTA count (16384 > 8192 > 1024); this probes one step
// further in that direction.

__device__ __forceinline__ void lif_lane(float imp, float m, float ru,
                                         float& psp, float& mo, float& ro, float& so)
{
    const float TIME = 5.0f;
    const float REFRAC_RESET = 7.0f;   // TIME + TAU_REFRAC
    const float V_THRESH = 1.0f;
    const float LEAK_AMT = 0.1f;       // 0.1 * DT

    float mi = (ru > TIME) ? 0.0f : imp;
    float nm = m + mi;
    nm = (nm > 0.0f) ? nm - LEAK_AMT : nm;
    bool sp = (nm >= V_THRESH);
    psp = sp ? V_THRESH : 0.0f;
    mo  = sp ? 0.0f : nm;
    ro  = sp ? REFRAC_RESET : ru;
    so  = sp ? TIME : 0.0f;
}

__global__ void __launch_bounds__(128) spike_layer_kernel(
    const float4* __restrict__ impulse,
    const float4* __restrict__ mem,
    const float4* __restrict__ refrac_until,
    float4* __restrict__ out_psp,
    float4* __restrict__ out_mem,
    float4* __restrict__ out_refrac,
    float4* __restrict__ out_spiketrain,
    int n4)
{
    int i = blockIdx.x * blockDim.x + threadIdx.x;
    if (i >= n4) return;

    float4 imp = __ldcs(&impulse[i]);
    float4 m   = __ldcs(&mem[i]);
    float4 ru  = __ldcs(&refrac_until[i]);

    float4 psp, mo, ro, so;
    lif_lane(imp.x, m.x, ru.x, psp.x, mo.x, ro.x, so.x);
    lif_lane(imp.y, m.y, ru.y, psp.y, mo.y, ro.y, so.y);
    lif_lane(imp.z, m.z, ru.z, psp.z, mo.z, ro.z, so.z);
    lif_lane(imp.w, m.w, ru.w, psp.w, mo.w, ro.w, so.w);

    __stcs(&out_psp[i],        psp);
    __stcs(&out_mem[i],        mo);
    __stcs(&out_refrac[i],     ro);
    __stcs(&out_spiketrain[i], so);
}

extern "C" void kernel_launch(void* const* d_in, const int* in_sizes, int n_in,
                              void* d_out, int out_size)
{
    const float* impulse      = (const float*)d_in[0];
    const float* mem          = (const float*)d_in[1];
    const float* refrac_until = (const float*)d_in[2];
    // d_in[3] (spiketrain) values are unused by the reference math.

    int n = in_sizes[0];          // 16,777,216
    int n4 = n / 4;               // 4,194,304 = 2^22

    float* out = (float*)d_out;   // [psp | mem | refrac | spiketrain], each n floats

    int threads = 128;
    int blocks = (n4 + threads - 1) / threads;   // 32768

    spike_layer_kernel<<<blocks, threads>>>(
        (const float4*)impulse,
        (const float4*)mem,
        (const float4*)refrac_until,
        (float4*)(out),
        (float4*)(out + (size_t)n),
        (float4*)(out + (size_t)2 * n),
        (float4*)(out + (size_t)3 * n),
        n4);
}